// round 11
// baseline (speedup 1.0000x reference)
#include <cuda_runtime.h>
#include <cstdint>

// Problem dims (fixed for this problem instance)
#define B_BATCH 16
#define L_SEQ   2048
#define D_DIM   256
#define K_CODES 1024
#define M_ROWS  (B_BATCH * L_SEQ)   // 32768

// GEMM-argmin tiling
#define BM 128
#define BN 128
#define BK 32
#define TM 8
#define TN 8
#define THREADS 256
#define AS_STRIDE (BM + 4)   // 132 — padded, transposed A: As[k][row]
#define BS_STRIDE (BN + 4)   // 132 — padded, transposed B: Bs[k][code]

// Scratch (device globals — no allocations allowed)
__device__ int   g_idx[M_ROWS];
__device__ float g_cbsq[K_CODES];
__device__ float g_ploss[M_ROWS / 8];
__device__ float g_pden[M_ROWS / 8];

// ---------------------------------------------------------------------------
// Packed fp32x2 helpers (Blackwell FFMA2 path — only reachable via PTX)
// ---------------------------------------------------------------------------
__device__ __forceinline__ void fma2(unsigned long long& d,
                                     unsigned long long a,
                                     unsigned long long b) {
    asm("fma.rn.f32x2 %0, %1, %2, %0;" : "+l"(d) : "l"(a), "l"(b));
}

__device__ __forceinline__ unsigned long long dupf(float x) {
    unsigned long long r;
    unsigned int u = __float_as_uint(x);
    asm("mov.b64 %0, {%1, %1};" : "=l"(r) : "r"(u));
    return r;
}

__device__ __forceinline__ float lo32(unsigned long long v) {
    return __uint_as_float((unsigned int)(v & 0xffffffffull));
}
__device__ __forceinline__ float hi32(unsigned long long v) {
    return __uint_as_float((unsigned int)(v >> 32));
}

// ---------------------------------------------------------------------------
// Kernel 0: per-code squared norms  cb_sq[k] = sum_d w[k][d]^2
// ---------------------------------------------------------------------------
__global__ void cbsq_kernel(const float* __restrict__ cb) {
    int warp = (blockIdx.x * blockDim.x + threadIdx.x) >> 5;
    int lane = threadIdx.x & 31;
    if (warp >= K_CODES) return;
    const float* row = cb + (size_t)warp * D_DIM;
    float s = 0.f;
#pragma unroll
    for (int i = 0; i < D_DIM / 32; i++) {
        float v = row[lane + i * 32];
        s += v * v;
    }
#pragma unroll
    for (int o = 16; o > 0; o >>= 1) s += __shfl_down_sync(0xffffffffu, s, o);
    if (lane == 0) g_cbsq[warp] = s;
}

// ---------------------------------------------------------------------------
// Kernel 1: fused GEMM + argmin.
// Block = 128 feature rows vs all 1024 codes. A (128x256) staged fully in smem
// (transposed); B streamed in 32x128 transposed tiles. 8x8 micro-tile per
// thread as 4x8 packed f32x2 accumulators (rows paired).
// ---------------------------------------------------------------------------
extern __shared__ float sm_dyn[];

__global__ void __launch_bounds__(THREADS, 1)
argmin_kernel(const float* __restrict__ feat, const float* __restrict__ cb) {
    float* As = sm_dyn;                               // [D_DIM][AS_STRIDE]
    float* Bs = As + D_DIM * AS_STRIDE;               // [BK][BS_STRIDE]
    float* Cs = Bs + BK * BS_STRIDE;                  // [K_CODES] cb_sq copy

    const int tid = threadIdx.x;
    const int tx = tid & 15;        // code group
    const int ty = tid >> 4;        // row group
    const int rowBase = blockIdx.x * BM;

    // cb_sq -> smem
#pragma unroll
    for (int i = 0; i < K_CODES / THREADS; i++)
        Cs[tid + i * THREADS] = g_cbsq[tid + i * THREADS];

    // Fill A transposed: As[d][row]. Mapping chosen for conflict-free STS
    // (consecutive lanes -> consecutive rows); global reads are 16B-granular
    // scattered, fine (feature block is only 128KB).
#pragma unroll
    for (int it = 0; it < (BM * D_DIM / 4) / THREADS; it++) {
        int p = tid + it * THREADS;
        int row = p & (BM - 1);
        int d4 = p >> 7;                               // p / BM
        const float4 v = *reinterpret_cast<const float4*>(
            feat + (size_t)(rowBase + row) * D_DIM + d4 * 4);
        As[(d4 * 4 + 0) * AS_STRIDE + row] = v.x;
        As[(d4 * 4 + 1) * AS_STRIDE + row] = v.y;
        As[(d4 * 4 + 2) * AS_STRIDE + row] = v.z;
        As[(d4 * 4 + 3) * AS_STRIDE + row] = v.w;
    }
    __syncthreads();

    float minv[TM];
    int   mini[TM];
#pragma unroll
    for (int i = 0; i < TM; i++) { minv[i] = 3.4e38f; mini[i] = 0; }

    for (int ct = 0; ct < K_CODES / BN; ct++) {
        unsigned long long acc2[TM / 2][TN];
#pragma unroll
        for (int i = 0; i < TM / 2; i++)
#pragma unroll
            for (int j = 0; j < TN; j++) acc2[i][j] = 0ull;

        for (int kt = 0; kt < D_DIM / BK; kt++) {
            // Fill B transposed: Bs[kk][code] (conflict-free STS)
#pragma unroll
            for (int it = 0; it < (BN * BK / 4) / THREADS; it++) {
                int p = tid + it * THREADS;
                int code = p & (BN - 1);
                int kk4 = p >> 7;
                const float4 v = *reinterpret_cast<const float4*>(
                    cb + (size_t)(ct * BN + code) * D_DIM + kt * BK + kk4 * 4);
                Bs[(kk4 * 4 + 0) * BS_STRIDE + code] = v.x;
                Bs[(kk4 * 4 + 1) * BS_STRIDE + code] = v.y;
                Bs[(kk4 * 4 + 2) * BS_STRIDE + code] = v.z;
                Bs[(kk4 * 4 + 3) * BS_STRIDE + code] = v.w;
            }
            __syncthreads();

#pragma unroll 8
            for (int kk = 0; kk < BK; kk++) {
                const int k = kt * BK + kk;
                // A: 8 contiguous rows -> 4 packed row-pairs, free from 64-bit loads
                const ulonglong2* ap = reinterpret_cast<const ulonglong2*>(
                    As + k * AS_STRIDE + ty * TM);
                ulonglong2 av0 = ap[0];
                ulonglong2 av1 = ap[1];
                unsigned long long a2[4] = {av0.x, av0.y, av1.x, av1.y};

                // B: 8 scalar codes, each duplicated into a packed pair
                const float4* bp = reinterpret_cast<const float4*>(
                    Bs + kk * BS_STRIDE + tx * TN);
                float4 bv0 = bp[0];
                float4 bv1 = bp[1];
                unsigned long long b2[8];
                b2[0] = dupf(bv0.x); b2[1] = dupf(bv0.y);
                b2[2] = dupf(bv0.z); b2[3] = dupf(bv0.w);
                b2[4] = dupf(bv1.x); b2[5] = dupf(bv1.y);
                b2[6] = dupf(bv1.z); b2[7] = dupf(bv1.w);

#pragma unroll
                for (int j = 0; j < TN; j++)
#pragma unroll
                    for (int i = 0; i < TM / 2; i++)
                        fma2(acc2[i][j], a2[i], b2[j]);
            }
            __syncthreads();
        }

        // dist = cb_sq - 2*dot ; running (min, argmin) per local row
#pragma unroll
        for (int j = 0; j < TN; j++) {
            int code = ct * BN + tx * TN + j;
            float cq = Cs[code];
#pragma unroll
            for (int i2 = 0; i2 < TM / 2; i2++) {
                float d0 = cq - 2.0f * lo32(acc2[i2][j]);
                float d1 = cq - 2.0f * hi32(acc2[i2][j]);
                int r0 = 2 * i2, r1 = 2 * i2 + 1;
                if (d0 < minv[r0]) { minv[r0] = d0; mini[r0] = code; }
                if (d1 < minv[r1]) { minv[r1] = d1; mini[r1] = code; }
            }
        }
    }

    // Cross-thread reduce: 16 tx-threads share each row. Reuse As region.
    float* redv = As;                                  // [BM][16]
    int*   redi = reinterpret_cast<int*>(As + BM * 16);
#pragma unroll
    for (int i = 0; i < TM; i++) {
        redv[(ty * TM + i) * 16 + tx] = minv[i];
        redi[(ty * TM + i) * 16 + tx] = mini[i];
    }
    __syncthreads();
    if (tid < BM) {
        float bv = redv[tid * 16];
        int   bi = redi[tid * 16];
#pragma unroll
        for (int t = 1; t < 16; t++) {
            float v = redv[tid * 16 + t];
            int  ix = redi[tid * 16 + t];
            if (v < bv || (v == bv && ix < bi)) { bv = v; bi = ix; }
        }
        g_idx[rowBase + tid] = bi;
    }
}

// ---------------------------------------------------------------------------
// Kernel 2: gather codebook rows, write quantized_st = f + (q - f) exactly as
// reference, accumulate per-block masked squared-error + mask sums
// (deterministic: no atomics).
// ---------------------------------------------------------------------------
__global__ void gather_loss_kernel(const float* __restrict__ feat,
                                   const float* __restrict__ mask,
                                   const float* __restrict__ cb,
                                   float* __restrict__ outq) {
    __shared__ float sl[8];
    __shared__ float sd[8];
    const int warp = threadIdx.x >> 5;
    const int lane = threadIdx.x & 31;
    const int r = blockIdx.x * 8 + warp;

    const int idx = g_idx[r];
    const float* f = feat + (size_t)r * D_DIM;
    const float* w = cb + (size_t)idx * D_DIM;
    float* o = outq + (size_t)r * D_DIM;

    float s = 0.f;
#pragma unroll
    for (int u = 0; u < 2; u++) {
        int c = lane * 4 + u * 128;
        float4 fv = *reinterpret_cast<const float4*>(f + c);
        float4 wv = *reinterpret_cast<const float4*>(w + c);
        float4 ov;
        ov.x = fv.x + (wv.x - fv.x);
        ov.y = fv.y + (wv.y - fv.y);
        ov.z = fv.z + (wv.z - fv.z);
        ov.w = fv.w + (wv.w - fv.w);
        *reinterpret_cast<float4*>(o + c) = ov;
        float dx = fv.x - wv.x, dy = fv.y - wv.y;
        float dz = fv.z - wv.z, dw = fv.w - wv.w;
        s += dx * dx + dy * dy + dz * dz + dw * dw;
    }
#pragma unroll
    for (int of = 16; of > 0; of >>= 1) s += __shfl_down_sync(0xffffffffu, s, of);
    if (lane == 0) {
        float m = mask[r];
        sl[warp] = s * m;
        sd[warp] = m;
    }
    __syncthreads();
    if (threadIdx.x == 0) {
        float L = 0.f, Dn = 0.f;
#pragma unroll
        for (int i = 0; i < 8; i++) { L += sl[i]; Dn += sd[i]; }
        g_ploss[blockIdx.x] = L;
        g_pden[blockIdx.x] = Dn;
    }
}

// ---------------------------------------------------------------------------
// Kernel 3: reduce partials per batch, write both losses (identical forward).
// ---------------------------------------------------------------------------
__global__ void finalize_kernel(float* __restrict__ out) {
    __shared__ float sl[256];
    __shared__ float sd[256];
    const int b = blockIdx.x, t = threadIdx.x;
    const int per = (M_ROWS / 8) / B_BATCH;   // 256 partials per batch
    sl[t] = g_ploss[b * per + t];
    sd[t] = g_pden[b * per + t];
    __syncthreads();
    for (int s = 128; s > 0; s >>= 1) {
        if (t < s) { sl[t] += sl[t + s]; sd[t] += sd[t + s]; }
        __syncthreads();
    }
    if (t == 0) {
        float loss = sl[0] / sd[0];
        size_t q = (size_t)M_ROWS * D_DIM;
        out[q + b] = loss;                 // quant_loss
        out[q + B_BATCH + b] = loss;       // commit_loss (numerically identical)
    }
}

// ---------------------------------------------------------------------------
extern "C" void kernel_launch(void* const* d_in, const int* in_sizes, int n_in,
                              void* d_out, int out_size) {
    const float* feat = (const float*)d_in[0];   // [16, 2048, 256] f32
    const float* mask = (const float*)d_in[1];   // [16, 2048] f32
    const float* cb   = (const float*)d_in[2];   // [1024, 256] f32
    float* out = (float*)d_out;

    constexpr size_t SMEM =
        (size_t)(D_DIM * AS_STRIDE + BK * BS_STRIDE + K_CODES) * sizeof(float);
    cudaFuncSetAttribute(argmin_kernel,
                         cudaFuncAttributeMaxDynamicSharedMemorySize, (int)SMEM);

    cbsq_kernel<<<K_CODES / 8, 256>>>(cb);
    argmin_kernel<<<M_ROWS / BM, THREADS, SMEM>>>(feat, cb);
    gather_loss_kernel<<<M_ROWS / 8, 256>>>(feat, mask, cb, out);
    finalize_kernel<<<B_BATCH, 256>>>(out);
}

// round 12
// speedup vs baseline: 1.0570x; 1.0570x over previous
#include <cuda_runtime.h>
#include <cstdint>

// Problem dims (fixed for this problem instance)
#define B_BATCH 16
#define L_SEQ   2048
#define D_DIM   256
#define K_CODES 1024
#define M_ROWS  (B_BATCH * L_SEQ)   // 32768

// GEMM-argmin tiling
#define BM 128
#define BN 128
#define BK 32
#define TM 8
#define TN 8
#define THREADS 256
#define AS_STRIDE (BM + 4)   // 132 — padded, transposed A: As[k][row]
#define BS_STRIDE (BN + 4)   // 132 — padded, transposed B: Bs[k][code]

// Scratch (device globals — no allocations allowed)
__device__ int   g_idx[M_ROWS];
__device__ float g_cbsq[K_CODES];
__device__ float g_ploss[M_ROWS / 8];
__device__ float g_pden[M_ROWS / 8];

// ---------------------------------------------------------------------------
// Packed fp32x2 helpers (Blackwell FFMA2 path — only reachable via PTX)
// ---------------------------------------------------------------------------
__device__ __forceinline__ void fma2(unsigned long long& d,
                                     unsigned long long a,
                                     unsigned long long b) {
    asm("fma.rn.f32x2 %0, %1, %2, %0;" : "+l"(d) : "l"(a), "l"(b));
}

__device__ __forceinline__ unsigned long long dupf(float x) {
    unsigned long long r;
    unsigned int u = __float_as_uint(x);
    asm("mov.b64 %0, {%1, %1};" : "=l"(r) : "r"(u));
    return r;
}

__device__ __forceinline__ float lo32(unsigned long long v) {
    return __uint_as_float((unsigned int)(v & 0xffffffffull));
}
__device__ __forceinline__ float hi32(unsigned long long v) {
    return __uint_as_float((unsigned int)(v >> 32));
}

// ---------------------------------------------------------------------------
// Kernel 0: per-code squared norms  cb_sq[k] = sum_d w[k][d]^2
// ---------------------------------------------------------------------------
__global__ void cbsq_kernel(const float* __restrict__ cb) {
    int warp = (blockIdx.x * blockDim.x + threadIdx.x) >> 5;
    int lane = threadIdx.x & 31;
    if (warp >= K_CODES) return;
    const float* row = cb + (size_t)warp * D_DIM;
    float s = 0.f;
#pragma unroll
    for (int i = 0; i < D_DIM / 32; i++) {
        float v = row[lane + i * 32];
        s += v * v;
    }
#pragma unroll
    for (int o = 16; o > 0; o >>= 1) s += __shfl_down_sync(0xffffffffu, s, o);
    if (lane == 0) g_cbsq[warp] = s;
}

// ---------------------------------------------------------------------------
// Kernel 1: fused GEMM + argmin.
// Block = 128 feature rows vs all 1024 codes. A (128x256) staged fully in smem
// (transposed); B streamed in 32x128 transposed tiles. 8x8 micro-tile per
// thread as 4x8 packed f32x2 accumulators (rows paired).
// ---------------------------------------------------------------------------
extern __shared__ float sm_dyn[];

__global__ void __launch_bounds__(THREADS, 1)
argmin_kernel(const float* __restrict__ feat, const float* __restrict__ cb) {
    float* As = sm_dyn;                               // [D_DIM][AS_STRIDE]
    float* Bs = As + D_DIM * AS_STRIDE;               // [BK][BS_STRIDE]
    float* Cs = Bs + BK * BS_STRIDE;                  // [K_CODES] cb_sq copy

    const int tid = threadIdx.x;
    const int tx = tid & 15;        // code group
    const int ty = tid >> 4;        // row group
    const int rowBase = blockIdx.x * BM;

    // cb_sq -> smem
#pragma unroll
    for (int i = 0; i < K_CODES / THREADS; i++)
        Cs[tid + i * THREADS] = g_cbsq[tid + i * THREADS];

    // Fill A transposed: As[d][row]. Mapping chosen for conflict-free STS
    // (consecutive lanes -> consecutive rows); global reads are 16B-granular
    // scattered, fine (feature block is only 128KB).
#pragma unroll
    for (int it = 0; it < (BM * D_DIM / 4) / THREADS; it++) {
        int p = tid + it * THREADS;
        int row = p & (BM - 1);
        int d4 = p >> 7;                               // p / BM
        const float4 v = *reinterpret_cast<const float4*>(
            feat + (size_t)(rowBase + row) * D_DIM + d4 * 4);
        As[(d4 * 4 + 0) * AS_STRIDE + row] = v.x;
        As[(d4 * 4 + 1) * AS_STRIDE + row] = v.y;
        As[(d4 * 4 + 2) * AS_STRIDE + row] = v.z;
        As[(d4 * 4 + 3) * AS_STRIDE + row] = v.w;
    }
    __syncthreads();

    float minv[TM];
    int   mini[TM];
#pragma unroll
    for (int i = 0; i < TM; i++) { minv[i] = 3.4e38f; mini[i] = 0; }

    for (int ct = 0; ct < K_CODES / BN; ct++) {
        unsigned long long acc2[TM / 2][TN];
#pragma unroll
        for (int i = 0; i < TM / 2; i++)
#pragma unroll
            for (int j = 0; j < TN; j++) acc2[i][j] = 0ull;

        for (int kt = 0; kt < D_DIM / BK; kt++) {
            // Fill B transposed: Bs[kk][code] (conflict-free STS)
#pragma unroll
            for (int it = 0; it < (BN * BK / 4) / THREADS; it++) {
                int p = tid + it * THREADS;
                int code = p & (BN - 1);
                int kk4 = p >> 7;
                const float4 v = *reinterpret_cast<const float4*>(
                    cb + (size_t)(ct * BN + code) * D_DIM + kt * BK + kk4 * 4);
                Bs[(kk4 * 4 + 0) * BS_STRIDE + code] = v.x;
                Bs[(kk4 * 4 + 1) * BS_STRIDE + code] = v.y;
                Bs[(kk4 * 4 + 2) * BS_STRIDE + code] = v.z;
                Bs[(kk4 * 4 + 3) * BS_STRIDE + code] = v.w;
            }
            __syncthreads();

#pragma unroll 8
            for (int kk = 0; kk < BK; kk++) {
                const int k = kt * BK + kk;
                // A: 8 contiguous rows -> 4 packed row-pairs, free from 64-bit loads
                const ulonglong2* ap = reinterpret_cast<const ulonglong2*>(
                    As + k * AS_STRIDE + ty * TM);
                ulonglong2 av0 = ap[0];
                ulonglong2 av1 = ap[1];
                unsigned long long a2[4] = {av0.x, av0.y, av1.x, av1.y};

                // B: 8 scalar codes, each duplicated into a packed pair
                const float4* bp = reinterpret_cast<const float4*>(
                    Bs + kk * BS_STRIDE + tx * TN);
                float4 bv0 = bp[0];
                float4 bv1 = bp[1];
                unsigned long long b2[8];
                b2[0] = dupf(bv0.x); b2[1] = dupf(bv0.y);
                b2[2] = dupf(bv0.z); b2[3] = dupf(bv0.w);
                b2[4] = dupf(bv1.x); b2[5] = dupf(bv1.y);
                b2[6] = dupf(bv1.z); b2[7] = dupf(bv1.w);

#pragma unroll
                for (int j = 0; j < TN; j++)
#pragma unroll
                    for (int i = 0; i < TM / 2; i++)
                        fma2(acc2[i][j], a2[i], b2[j]);
            }
            __syncthreads();
        }

        // dist = cb_sq - 2*dot ; running (min, argmin) per local row
#pragma unroll
        for (int j = 0; j < TN; j++) {
            int code = ct * BN + tx * TN + j;
            float cq = Cs[code];
#pragma unroll
            for (int i2 = 0; i2 < TM / 2; i2++) {
                float d0 = cq - 2.0f * lo32(acc2[i2][j]);
                float d1 = cq - 2.0f * hi32(acc2[i2][j]);
                int r0 = 2 * i2, r1 = 2 * i2 + 1;
                if (d0 < minv[r0]) { minv[r0] = d0; mini[r0] = code; }
                if (d1 < minv[r1]) { minv[r1] = d1; mini[r1] = code; }
            }
        }
    }

    // Cross-thread reduce: 16 tx-threads share each row. Reuse As region.
    float* redv = As;                                  // [BM][16]
    int*   redi = reinterpret_cast<int*>(As + BM * 16);
#pragma unroll
    for (int i = 0; i < TM; i++) {
        redv[(ty * TM + i) * 16 + tx] = minv[i];
        redi[(ty * TM + i) * 16 + tx] = mini[i];
    }
    __syncthreads();
    if (tid < BM) {
        float bv = redv[tid * 16];
        int   bi = redi[tid * 16];
#pragma unroll
        for (int t = 1; t < 16; t++) {
            float v = redv[tid * 16 + t];
            int  ix = redi[tid * 16 + t];
            if (v < bv || (v == bv && ix < bi)) { bv = v; bi = ix; }
        }
        g_idx[rowBase + tid] = bi;
    }
}

// ---------------------------------------------------------------------------
// Kernel 2: gather codebook rows, write quantized_st = f + (q - f) exactly as
// reference, accumulate per-block masked squared-error + mask sums
// (deterministic: no atomics).
// ---------------------------------------------------------------------------
__global__ void gather_loss_kernel(const float* __restrict__ feat,
                                   const float* __restrict__ mask,
                                   const float* __restrict__ cb,
                                   float* __restrict__ outq) {
    __shared__ float sl[8];
    __shared__ float sd[8];
    const int warp = threadIdx.x >> 5;
    const int lane = threadIdx.x & 31;
    const int r = blockIdx.x * 8 + warp;

    const int idx = g_idx[r];
    const float* f = feat + (size_t)r * D_DIM;
    const float* w = cb + (size_t)idx * D_DIM;
    float* o = outq + (size_t)r * D_DIM;

    float s = 0.f;
#pragma unroll
    for (int u = 0; u < 2; u++) {
        int c = lane * 4 + u * 128;
        float4 fv = *reinterpret_cast<const float4*>(f + c);
        float4 wv = *reinterpret_cast<const float4*>(w + c);
        float4 ov;
        ov.x = fv.x + (wv.x - fv.x);
        ov.y = fv.y + (wv.y - fv.y);
        ov.z = fv.z + (wv.z - fv.z);
        ov.w = fv.w + (wv.w - fv.w);
        *reinterpret_cast<float4*>(o + c) = ov;
        float dx = fv.x - wv.x, dy = fv.y - wv.y;
        float dz = fv.z - wv.z, dw = fv.w - wv.w;
        s += dx * dx + dy * dy + dz * dz + dw * dw;
    }
#pragma unroll
    for (int of = 16; of > 0; of >>= 1) s += __shfl_down_sync(0xffffffffu, s, of);
    if (lane == 0) {
        float m = mask[r];
        sl[warp] = s * m;
        sd[warp] = m;
    }
    __syncthreads();
    if (threadIdx.x == 0) {
        float L = 0.f, Dn = 0.f;
#pragma unroll
        for (int i = 0; i < 8; i++) { L += sl[i]; Dn += sd[i]; }
        g_ploss[blockIdx.x] = L;
        g_pden[blockIdx.x] = Dn;
    }
}

// ---------------------------------------------------------------------------
// Kernel 3: reduce partials per batch, write both losses (identical forward).
// ---------------------------------------------------------------------------
__global__ void finalize_kernel(float* __restrict__ out) {
    __shared__ float sl[256];
    __shared__ float sd[256];
    const int b = blockIdx.x, t = threadIdx.x;
    const int per = (M_ROWS / 8) / B_BATCH;   // 256 partials per batch
    sl[t] = g_ploss[b * per + t];
    sd[t] = g_pden[b * per + t];
    __syncthreads();
    for (int s = 128; s > 0; s >>= 1) {
        if (t < s) { sl[t] += sl[t + s]; sd[t] += sd[t + s]; }
        __syncthreads();
    }
    if (t == 0) {
        float loss = sl[0] / sd[0];
        size_t q = (size_t)M_ROWS * D_DIM;
        out[q + b] = loss;                 // quant_loss
        out[q + B_BATCH + b] = loss;       // commit_loss (numerically identical)
    }
}

// ---------------------------------------------------------------------------
extern "C" void kernel_launch(void* const* d_in, const int* in_sizes, int n_in,
                              void* d_out, int out_size) {
    const float* feat = (const float*)d_in[0];   // [16, 2048, 256] f32
    const float* mask = (const float*)d_in[1];   // [16, 2048] f32
    const float* cb   = (const float*)d_in[2];   // [1024, 256] f32
    float* out = (float*)d_out;

    constexpr size_t SMEM =
        (size_t)(D_DIM * AS_STRIDE + BK * BS_STRIDE + K_CODES) * sizeof(float);
    cudaFuncSetAttribute(argmin_kernel,
                         cudaFuncAttributeMaxDynamicSharedMemorySize, (int)SMEM);

    cbsq_kernel<<<K_CODES / 8, 256>>>(cb);
    argmin_kernel<<<M_ROWS / BM, THREADS, SMEM>>>(feat, cb);
    gather_loss_kernel<<<M_ROWS / 8, 256>>>(feat, mask, cb, out);
    finalize_kernel<<<B_BATCH, 256>>>(out);
}

// round 14
// speedup vs baseline: 1.6760x; 1.5856x over previous
#include <cuda_runtime.h>
#include <cuda_fp16.h>
#include <cstdint>

// Problem dims (fixed)
#define B_BATCH 16
#define L_SEQ   2048
#define D_DIM   256
#define K_CODES 1024
#define M_ROWS  (B_BATCH * L_SEQ)   // 32768

// Scratch (device globals — no allocations allowed)
__device__ int    g_idx[M_ROWS];
__device__ float  g_cbsq[K_CODES];
__device__ __half g_b2[K_CODES * 2 * D_DIM];   // [1024][512] = [hi(256) | lo(256)]
__device__ float  g_ploss[M_ROWS / 8];
__device__ float  g_pden[M_ROWS / 8];

// ---------------------------------------------------------------------------
// GEMM kernel geometry
// ---------------------------------------------------------------------------
#define ASTRIDE 520                        // halfs per A row (pad: 1040B, 16B-mult)
#define BSTRIDE 136                        // halfs per B chunk row (272B)
#define A_BYTES (128 * ASTRIDE * 2)        // 133120
#define B_BYTES (128 * BSTRIDE * 2)        // 34816
#define SM_A    0
#define SM_B    A_BYTES
#define SM_CS   (SM_B + 2 * B_BYTES)       // 202752
#define SMEM_TOTAL (SM_CS + 4096)          // 206848

// ---------------------------------------------------------------------------
// PTX helpers (baseline sm_80+ instructions only — NO tcgen05)
// ---------------------------------------------------------------------------
__device__ __forceinline__ uint32_t smem_u32(const void* p) {
    uint32_t a;
    asm("{ .reg .u64 t; cvta.to.shared.u64 t, %1; cvt.u32.u64 %0, t; }"
        : "=r"(a) : "l"(p));
    return a;
}

__device__ __forceinline__ void cp16(uint32_t dst, const void* src) {
    asm volatile("cp.async.cg.shared.global [%0], [%1], 16;"
                 :: "r"(dst), "l"(src) : "memory");
}
#define CP_COMMIT() asm volatile("cp.async.commit_group;" ::: "memory")
#define CP_WAIT(n)  asm volatile("cp.async.wait_group %0;" :: "n"(n) : "memory")

__device__ __forceinline__ void ldsm4(uint32_t* r, uint32_t addr) {
    asm volatile("ldmatrix.sync.aligned.m8n8.x4.shared.b16 {%0,%1,%2,%3}, [%4];"
                 : "=r"(r[0]), "=r"(r[1]), "=r"(r[2]), "=r"(r[3]) : "r"(addr));
}

__device__ __forceinline__ void mma16816(float* c, const uint32_t* a,
                                         uint32_t b0, uint32_t b1) {
    asm volatile(
        "mma.sync.aligned.m16n8k16.row.col.f32.f16.f16.f32 "
        "{%0,%1,%2,%3}, {%4,%5,%6,%7}, {%8,%9}, {%0,%1,%2,%3};"
        : "+f"(c[0]), "+f"(c[1]), "+f"(c[2]), "+f"(c[3])
        : "r"(a[0]), "r"(a[1]), "r"(a[2]), "r"(a[3]), "r"(b0), "r"(b1));
}

__device__ __forceinline__ void split_h(float x, __half& hi, __half& lo) {
    hi = __float2half_rn(x);
    lo = __float2half_rn(x - __half2float(hi));
}

// ---------------------------------------------------------------------------
// Kernel 0a: per-code squared norms (exact fp32)
// ---------------------------------------------------------------------------
__global__ void cbsq_kernel(const float* __restrict__ cb) {
    int warp = (blockIdx.x * blockDim.x + threadIdx.x) >> 5;
    int lane = threadIdx.x & 31;
    if (warp >= K_CODES) return;
    const float* row = cb + (size_t)warp * D_DIM;
    float s = 0.f;
#pragma unroll
    for (int i = 0; i < D_DIM / 32; i++) {
        float v = row[lane + i * 32];
        s += v * v;
    }
#pragma unroll
    for (int o = 16; o > 0; o >>= 1) s += __shfl_down_sync(0xffffffffu, s, o);
    if (lane == 0) g_cbsq[warp] = s;
}

// ---------------------------------------------------------------------------
// Kernel 0b: split codebook fp32 -> fp16 hi|lo, layout [1024][hi256|lo256]
// ---------------------------------------------------------------------------
__global__ void prep_b_kernel(const float* __restrict__ cb) {
    int u = blockIdx.x * 256 + threadIdx.x;    // 65536 quads
    int row = u >> 6;
    int q = u & 63;
    float4 v = *reinterpret_cast<const float4*>(cb + (size_t)row * D_DIM + q * 4);
    __half h0, h1, h2, h3, l0, l1, l2, l3;
    split_h(v.x, h0, l0); split_h(v.y, h1, l1);
    split_h(v.z, h2, l2); split_h(v.w, h3, l3);
    __half* dh = g_b2 + (size_t)row * 512 + q * 4;
    __half* dl = dh + 256;
    *reinterpret_cast<__half2*>(dh)     = __halves2half2(h0, h1);
    *reinterpret_cast<__half2*>(dh + 2) = __halves2half2(h2, h3);
    *reinterpret_cast<__half2*>(dl)     = __halves2half2(l0, l1);
    *reinterpret_cast<__half2*>(dl + 2) = __halves2half2(l2, l3);
}

// ---------------------------------------------------------------------------
// Kernel 1: fp16x4-split HMMA GEMM + fused argmin.
// CTA: 128 rows x 1024 codes. 8 warps, warp tile 32x64. Effective K = 1024
// (4 segments: ah*bh, ah*bl, al*bh, al*bl) in 8 chunks of 128 halfs,
// double-buffered via cp.async.
// ---------------------------------------------------------------------------
__global__ void __launch_bounds__(256, 1)
vq_mma_kernel(const float* __restrict__ feat) {
    extern __shared__ char smem[];
    __half* As = reinterpret_cast<__half*>(smem + SM_A);
    float* scs = reinterpret_cast<float*>(smem + SM_CS);
    const uint32_t sb = smem_u32(smem);

    const int tid = threadIdx.x;
    const int wid = tid >> 5;
    const int lane = tid & 31;
    const int gid = lane >> 2;         // row group within fragment
    const int tig = lane & 3;          // col-pair within fragment
    const int wm = wid & 3;            // warp m-row (0..3) -> rows wm*32
    const int wn = wid >> 2;           // warp n-col (0..1) -> cols wn*64
    const int rowBase = blockIdx.x * 128;

    // cb_sq -> smem
#pragma unroll
    for (int i = 0; i < K_CODES / 256; i++)
        scs[tid + i * 256] = g_cbsq[tid + i * 256];

    // A fill + fp16 split: 128 rows x 256 fp32 -> [row][ah(0:256) | al(256:512)]
#pragma unroll
    for (int it = 0; it < 32; it++) {
        int u = tid + it * 256;          // 8192 quads
        int row = u >> 6;
        int q = u & 63;
        float4 v = *reinterpret_cast<const float4*>(
            feat + (size_t)(rowBase + row) * D_DIM + q * 4);
        __half h0, h1, h2, h3, l0, l1, l2, l3;
        split_h(v.x, h0, l0); split_h(v.y, h1, l1);
        split_h(v.z, h2, l2); split_h(v.w, h3, l3);
        __half2* ph = reinterpret_cast<__half2*>(As + row * ASTRIDE + q * 4);
        __half2* pl = reinterpret_cast<__half2*>(As + row * ASTRIDE + 256 + q * 4);
        ph[0] = __halves2half2(h0, h1);
        ph[1] = __halves2half2(h2, h3);
        pl[0] = __halves2half2(l0, l1);
        pl[1] = __halves2half2(l2, l3);
    }
    __syncthreads();

    // ldmatrix base addresses (bytes)
    // A x4: lanes 0-15 rows (lane&15), lanes 16-31 same rows at k+8
    const uint32_t aAddr = sb + SM_A +
        ((uint32_t)((wm * 32 + (lane & 15)) * ASTRIDE + (lane >> 4) * 8) * 2u);
    // B x4: mat0 n0-7@k0, mat1 n0-7@k8, mat2 n8-15@k0, mat3 n8-15@k8
    const int n_off = (lane & 7) + ((lane >> 4) & 1) * 8;
    const int k_off = ((lane >> 3) & 1) * 8;
    const uint32_t bAddr = sb + SM_B +
        ((uint32_t)((wn * 64 + n_off) * BSTRIDE + k_off) * 2u);

    float bestv[4] = {3.4e38f, 3.4e38f, 3.4e38f, 3.4e38f};
    int   besti[4] = {0, 0, 0, 0};

    // chunk c (0..7): seg = c>>1; A col base / B col base in the 512-half space
    auto acol0 = [](int c) { return ((c >> 2) & 1) * 256 + (c & 1) * 128; };
    auto bcol0 = [](int c) { return ((c >> 1) & 1) * 256 + (c & 1) * 128; };

    const int pr = tid >> 1;             // prefetch row 0..127
    const int pc = (tid & 1) * 64;       // prefetch col half (halfs)
    const uint32_t pdst0 = sb + SM_B + (uint32_t)((pr * BSTRIDE + pc) * 2);

    for (int nt = 0; nt < 8; nt++) {
        const __half* bsrc = g_b2 + (size_t)(nt * 128) * 512;

        float acc[2][8][4];
#pragma unroll
        for (int i = 0; i < 2; i++)
#pragma unroll
            for (int j = 0; j < 8; j++)
#pragma unroll
                for (int x = 0; x < 4; x++) acc[i][j][x] = 0.f;

        // prefetch chunk 0 -> buf 0
        {
            const __half* s = bsrc + (size_t)pr * 512 + bcol0(0) + pc;
#pragma unroll
            for (int i = 0; i < 8; i++) cp16(pdst0 + i * 16, s + i * 8);
            CP_COMMIT();
        }

#pragma unroll 1
        for (int c = 0; c < 8; c++) {
            if (c < 7) {
                const int nb = (c + 1) & 1;
                const __half* s = bsrc + (size_t)pr * 512 + bcol0(c + 1) + pc;
                const uint32_t d = pdst0 + nb * B_BYTES;
#pragma unroll
                for (int i = 0; i < 8; i++) cp16(d + i * 16, s + i * 8);
                CP_COMMIT();
                CP_WAIT(1);
            } else {
                CP_WAIT(0);
            }
            __syncthreads();

            const uint32_t ab = aAddr + (uint32_t)(acol0(c) * 2);
            const uint32_t bb = bAddr + (uint32_t)((c & 1) * B_BYTES);
#pragma unroll
            for (int ks = 0; ks < 8; ks++) {
                uint32_t a0[4], a1[4];
                ldsm4(a0, ab + ks * 32);
                ldsm4(a1, ab + ks * 32 + 16 * ASTRIDE * 2);
#pragma unroll
                for (int jj = 0; jj < 4; jj++) {
                    uint32_t b[4];
                    ldsm4(b, bb + ks * 32 + jj * 16 * BSTRIDE * 2);
                    mma16816(acc[0][2 * jj],     a0, b[0], b[1]);
                    mma16816(acc[0][2 * jj + 1], a0, b[2], b[3]);
                    mma16816(acc[1][2 * jj],     a1, b[0], b[1]);
                    mma16816(acc[1][2 * jj + 1], a1, b[2], b[3]);
                }
            }
            __syncthreads();
        }

        // Epilogue: dist = cb_sq - 2*acc ; per-lane running argmin
        const int nbase = nt * 128 + wn * 64 + 2 * tig;
#pragma unroll
        for (int j = 0; j < 8; j++) {
            const int n0 = nbase + j * 8;
            const float cq0 = scs[n0];
            const float cq1 = scs[n0 + 1];
#pragma unroll
            for (int i = 0; i < 2; i++) {
                const int s0 = i * 2, s1 = i * 2 + 1;
                float d;
                d = cq0 - 2.f * acc[i][j][0];
                if (d < bestv[s0]) { bestv[s0] = d; besti[s0] = n0; }
                d = cq1 - 2.f * acc[i][j][1];
                if (d < bestv[s0]) { bestv[s0] = d; besti[s0] = n0 + 1; }
                d = cq0 - 2.f * acc[i][j][2];
                if (d < bestv[s1]) { bestv[s1] = d; besti[s1] = n0; }
                d = cq1 - 2.f * acc[i][j][3];
                if (d < bestv[s1]) { bestv[s1] = d; besti[s1] = n0 + 1; }
            }
        }
    }

    // Reduce over the 4 tig-lanes sharing each row (tie -> lower index)
#pragma unroll
    for (int o = 1; o < 4; o <<= 1) {
#pragma unroll
        for (int s = 0; s < 4; s++) {
            float ov = __shfl_xor_sync(0xffffffffu, bestv[s], o);
            int   oi = __shfl_xor_sync(0xffffffffu, besti[s], o);
            if (ov < bestv[s] || (ov == bestv[s] && oi < besti[s])) {
                bestv[s] = ov; besti[s] = oi;
            }
        }
    }

    // Cross warp-column reduce via smem (reuse B region)
    __syncthreads();
    float* rv = reinterpret_cast<float*>(smem + SM_B);          // [128][2]
    int*   ri = reinterpret_cast<int*>(smem + SM_B + 1024);     // [128][2]
    if (tig == 0) {
#pragma unroll
        for (int s = 0; s < 4; s++) {
            int row = wm * 32 + (s >> 1) * 16 + (s & 1) * 8 + gid;
            rv[row * 2 + wn] = bestv[s];
            ri[row * 2 + wn] = besti[s];
        }
    }
    __syncthreads();
    if (tid < 128) {
        float v0 = rv[tid * 2], v1 = rv[tid * 2 + 1];
        int i0 = ri[tid * 2], i1 = ri[tid * 2 + 1];
        int best = (v1 < v0 || (v1 == v0 && i1 < i0)) ? i1 : i0;
        g_idx[rowBase + tid] = best;
    }
}

// ---------------------------------------------------------------------------
// Kernel 2: gather + quantized_st + per-block masked losses (deterministic)
// ---------------------------------------------------------------------------
__global__ void gather_loss_kernel(const float* __restrict__ feat,
                                   const float* __restrict__ mask,
                                   const float* __restrict__ cb,
                                   float* __restrict__ outq) {
    __shared__ float sl[8];
    __shared__ float sd[8];
    const int warp = threadIdx.x >> 5;
    const int lane = threadIdx.x & 31;
    const int r = blockIdx.x * 8 + warp;

    const int idx = g_idx[r];
    const float* f = feat + (size_t)r * D_DIM;
    const float* w = cb + (size_t)idx * D_DIM;
    float* o = outq + (size_t)r * D_DIM;

    float s = 0.f;
#pragma unroll
    for (int u = 0; u < 2; u++) {
        int c = lane * 4 + u * 128;
        float4 fv = *reinterpret_cast<const float4*>(f + c);
        float4 wv = *reinterpret_cast<const float4*>(w + c);
        float4 ov;
        ov.x = fv.x + (wv.x - fv.x);
        ov.y = fv.y + (wv.y - fv.y);
        ov.z = fv.z + (wv.z - fv.z);
        ov.w = fv.w + (wv.w - fv.w);
        *reinterpret_cast<float4*>(o + c) = ov;
        float dx = fv.x - wv.x, dy = fv.y - wv.y;
        float dz = fv.z - wv.z, dw = fv.w - wv.w;
        s += dx * dx + dy * dy + dz * dz + dw * dw;
    }
#pragma unroll
    for (int of = 16; of > 0; of >>= 1) s += __shfl_down_sync(0xffffffffu, s, of);
    if (lane == 0) {
        float m = mask[r];
        sl[warp] = s * m;
        sd[warp] = m;
    }
    __syncthreads();
    if (threadIdx.x == 0) {
        float L = 0.f, Dn = 0.f;
#pragma unroll
        for (int i = 0; i < 8; i++) { L += sl[i]; Dn += sd[i]; }
        g_ploss[blockIdx.x] = L;
        g_pden[blockIdx.x] = Dn;
    }
}

// ---------------------------------------------------------------------------
// Kernel 3: per-batch reduce, write both losses
// ---------------------------------------------------------------------------
__global__ void finalize_kernel(float* __restrict__ out) {
    __shared__ float sl[256];
    __shared__ float sd[256];
    const int b = blockIdx.x, t = threadIdx.x;
    const int per = (M_ROWS / 8) / B_BATCH;   // 256
    sl[t] = g_ploss[b * per + t];
    sd[t] = g_pden[b * per + t];
    __syncthreads();
    for (int s = 128; s > 0; s >>= 1) {
        if (t < s) { sl[t] += sl[t + s]; sd[t] += sd[t + s]; }
        __syncthreads();
    }
    if (t == 0) {
        float loss = sl[0] / sd[0];
        size_t q = (size_t)M_ROWS * D_DIM;
        out[q + b] = loss;                 // quant_loss
        out[q + B_BATCH + b] = loss;       // commit_loss (numerically identical)
    }
}

// ---------------------------------------------------------------------------
extern "C" void kernel_launch(void* const* d_in, const int* in_sizes, int n_in,
                              void* d_out, int out_size) {
    const float* feat = (const float*)d_in[0];   // [16, 2048, 256] f32
    const float* mask = (const float*)d_in[1];   // [16, 2048] f32
    const float* cb   = (const float*)d_in[2];   // [1024, 256] f32
    float* out = (float*)d_out;

    cudaFuncSetAttribute(vq_mma_kernel,
                         cudaFuncAttributeMaxDynamicSharedMemorySize, SMEM_TOTAL);

    cbsq_kernel<<<K_CODES / 8, 256>>>(cb);
    prep_b_kernel<<<K_CODES * D_DIM / 4 / 256, 256>>>(cb);
    vq_mma_kernel<<<M_ROWS / 128, 256, SMEM_TOTAL>>>(feat);
    gather_loss_kernel<<<M_ROWS / 8, 256>>>(feat, mask, cb, out);
    finalize_kernel<<<B_BATCH, 256>>>(out);
}

// round 15
// speedup vs baseline: 2.1362x; 1.2746x over previous
#include <cuda_runtime.h>
#include <cuda_fp16.h>
#include <cstdint>

// Problem dims (fixed)
#define B_BATCH 16
#define L_SEQ   2048
#define D_DIM   256
#define K_CODES 1024
#define M_ROWS  (B_BATCH * L_SEQ)   // 32768

// Scratch (device globals — no allocations allowed)
__device__ int    g_idx[M_ROWS];
__device__ float  g_cbsq[K_CODES];
__device__ __half g_b2[K_CODES * 2 * D_DIM];   // [1024][512] = [hi(256) | lo(256)]
__device__ float  g_ploss[M_ROWS / 8];
__device__ float  g_pden[M_ROWS / 8];

// ---------------------------------------------------------------------------
// GEMM kernel geometry
// ---------------------------------------------------------------------------
#define ASTRIDE 520                        // halfs/row; 260 words ≡ 4 mod 32 (conflict-free ldsm)
#define BSTRIDE 136                        // halfs/row; 68 words ≡ 4 mod 32
#define A_BYTES (128 * ASTRIDE * 2)        // 133120
#define B_BYTES (128 * BSTRIDE * 2)        // 34816
#define SM_A    0
#define SM_B    A_BYTES
#define SM_CS   (SM_B + 2 * B_BYTES)       // 202752
#define SMEM_TOTAL (SM_CS + 4096)          // 206848

#define NSTEPS 48                          // 8 n-tiles x 6 chunks (3 segments)

// ---------------------------------------------------------------------------
// PTX helpers (baseline sm_80+ instructions only — NO tcgen05)
// ---------------------------------------------------------------------------
__device__ __forceinline__ uint32_t smem_u32(const void* p) {
    uint32_t a;
    asm("{ .reg .u64 t; cvta.to.shared.u64 t, %1; cvt.u32.u64 %0, t; }"
        : "=r"(a) : "l"(p));
    return a;
}

__device__ __forceinline__ void cp16(uint32_t dst, const void* src) {
    asm volatile("cp.async.cg.shared.global [%0], [%1], 16;"
                 :: "r"(dst), "l"(src) : "memory");
}
#define CP_COMMIT() asm volatile("cp.async.commit_group;" ::: "memory")
#define CP_WAIT(n)  asm volatile("cp.async.wait_group %0;" :: "n"(n) : "memory")

__device__ __forceinline__ void ldsm4(uint32_t* r, uint32_t addr) {
    asm volatile("ldmatrix.sync.aligned.m8n8.x4.shared.b16 {%0,%1,%2,%3}, [%4];"
                 : "=r"(r[0]), "=r"(r[1]), "=r"(r[2]), "=r"(r[3]) : "r"(addr));
}

__device__ __forceinline__ void mma16816(float* c, const uint32_t* a,
                                         uint32_t b0, uint32_t b1) {
    asm volatile(
        "mma.sync.aligned.m16n8k16.row.col.f32.f16.f16.f32 "
        "{%0,%1,%2,%3}, {%4,%5,%6,%7}, {%8,%9}, {%0,%1,%2,%3};"
        : "+f"(c[0]), "+f"(c[1]), "+f"(c[2]), "+f"(c[3])
        : "r"(a[0]), "r"(a[1]), "r"(a[2]), "r"(a[3]), "r"(b0), "r"(b1));
}

__device__ __forceinline__ void split_h(float x, __half& hi, __half& lo) {
    hi = __float2half_rn(x);
    lo = __float2half_rn(x - __half2float(hi));
}

union H8 {
    __half h[8];
    uint4 u;
};

// ---------------------------------------------------------------------------
// Kernel 0: merged codebook prep — per-row norm (exact fp32) + fp16 hi|lo
// split into g_b2[1024][hi256|lo256]. One warp per codebook row.
// ---------------------------------------------------------------------------
__global__ void prep_kernel(const float* __restrict__ cb) {
    const int w = (blockIdx.x * blockDim.x + threadIdx.x) >> 5;   // 0..1023
    const int lane = threadIdx.x & 31;
    const float* row = cb + (size_t)w * D_DIM;
    float4 v0 = *reinterpret_cast<const float4*>(row + lane * 8);
    float4 v1 = *reinterpret_cast<const float4*>(row + lane * 8 + 4);

    float s = v0.x * v0.x + v0.y * v0.y + v0.z * v0.z + v0.w * v0.w +
              v1.x * v1.x + v1.y * v1.y + v1.z * v1.z + v1.w * v1.w;
#pragma unroll
    for (int o = 16; o > 0; o >>= 1) s += __shfl_down_sync(0xffffffffu, s, o);
    if (lane == 0) g_cbsq[w] = s;

    H8 hh, ll;
    split_h(v0.x, hh.h[0], ll.h[0]); split_h(v0.y, hh.h[1], ll.h[1]);
    split_h(v0.z, hh.h[2], ll.h[2]); split_h(v0.w, hh.h[3], ll.h[3]);
    split_h(v1.x, hh.h[4], ll.h[4]); split_h(v1.y, hh.h[5], ll.h[5]);
    split_h(v1.z, hh.h[6], ll.h[6]); split_h(v1.w, hh.h[7], ll.h[7]);
    __half* dh = g_b2 + (size_t)w * 512 + lane * 8;
    *reinterpret_cast<uint4*>(dh) = hh.u;
    *reinterpret_cast<uint4*>(dh + 256) = ll.u;
}

// ---------------------------------------------------------------------------
// Kernel 1: fp16x3-split HMMA GEMM + fused argmin.
// CTA: 128 rows x 1024 codes. 8 warps, warp tile 32x64. Effective K = 768
// (segments ah*bh, ah*bl, al*bh; lo*lo dropped — bounded by ~6e-5 vs O(1)
// argmin gaps). Flattened 48-step chunk pipeline, cp.async double-buffered
// continuously across n-tile boundaries.
// ---------------------------------------------------------------------------
__global__ void __launch_bounds__(256, 1)
vq_mma_kernel(const float* __restrict__ feat) {
    extern __shared__ char smem[];
    __half* As = reinterpret_cast<__half*>(smem + SM_A);
    float* scs = reinterpret_cast<float*>(smem + SM_CS);
    const uint32_t sb = smem_u32(smem);

    const int tid = threadIdx.x;
    const int wid = tid >> 5;
    const int lane = tid & 31;
    const int gid = lane >> 2;         // row group within fragment
    const int tig = lane & 3;          // col-pair within fragment
    const int wm = wid & 3;            // warp m-row (0..3) -> rows wm*32
    const int wn = wid >> 2;           // warp n-col (0..1) -> cols wn*64
    const int rowBase = blockIdx.x * 128;

    // cb_sq -> smem
#pragma unroll
    for (int i = 0; i < K_CODES / 256; i++)
        scs[tid + i * 256] = g_cbsq[tid + i * 256];

    // A fill + fp16 split: 128 rows x 256 fp32 -> [row][ah(0:256) | al(256:512)]
#pragma unroll
    for (int it = 0; it < 32; it++) {
        int u = tid + it * 256;          // 8192 quads
        int row = u >> 6;
        int q = u & 63;
        float4 v = *reinterpret_cast<const float4*>(
            feat + (size_t)(rowBase + row) * D_DIM + q * 4);
        __half h0, h1, h2, h3, l0, l1, l2, l3;
        split_h(v.x, h0, l0); split_h(v.y, h1, l1);
        split_h(v.z, h2, l2); split_h(v.w, h3, l3);
        __half2* ph = reinterpret_cast<__half2*>(As + row * ASTRIDE + q * 4);
        __half2* pl = reinterpret_cast<__half2*>(As + row * ASTRIDE + 256 + q * 4);
        ph[0] = __halves2half2(h0, h1);
        ph[1] = __halves2half2(h2, h3);
        pl[0] = __halves2half2(l0, l1);
        pl[1] = __halves2half2(l2, l3);
    }
    __syncthreads();

    // ldmatrix base addresses (bytes)
    const uint32_t aAddr = sb + SM_A +
        ((uint32_t)((wm * 32 + (lane & 15)) * ASTRIDE + (lane >> 4) * 8) * 2u);
    const int n_off = (lane & 7) + ((lane >> 4) & 1) * 8;
    const int k_off = ((lane >> 3) & 1) * 8;
    const uint32_t bAddr = sb + SM_B +
        ((uint32_t)((wn * 64 + n_off) * BSTRIDE + k_off) * 2u);

    float bestv[4] = {3.4e38f, 3.4e38f, 3.4e38f, 3.4e38f};
    int   besti[4] = {0, 0, 0, 0};

    // Chunk c (0..5) within an n-tile: c<2 -> ah*bh, c in 2..3 -> ah*bl,
    // c in 4..5 -> al*bh. Columns are halfs in the 512-wide split space.
    auto acol = [](int c) { return ((c >> 2) ? 256 : 0) + (c & 1) * 128; };
    auto bcol = [](int c) { return (((c >> 1) == 1) ? 256 : 0) + (c & 1) * 128; };

    const int pr = tid >> 1;             // prefetch row 0..127
    const int pc = (tid & 1) * 64;       // prefetch col half (halfs)
    const uint32_t pdst0 = sb + SM_B + (uint32_t)((pr * BSTRIDE + pc) * 2);

    float acc[2][8][4];
#pragma unroll
    for (int i = 0; i < 2; i++)
#pragma unroll
        for (int j = 0; j < 8; j++)
#pragma unroll
            for (int x = 0; x < 4; x++) acc[i][j][x] = 0.f;

    // prefetch step 0 -> buf 0
    {
        const __half* s = g_b2 + (size_t)pr * 512 + bcol(0) + pc;
#pragma unroll
        for (int i = 0; i < 8; i++) cp16(pdst0 + i * 16, s + i * 8);
        CP_COMMIT();
    }

#pragma unroll 1
    for (int step = 0; step < NSTEPS; step++) {
        const int nt = step / 6;
        const int c  = step - nt * 6;

        if (step < NSTEPS - 1) {
            const int s2 = step + 1;
            const int nt2 = s2 / 6;
            const int c2 = s2 - nt2 * 6;
            const __half* s = g_b2 + (size_t)(nt2 * 128 + pr) * 512 + bcol(c2) + pc;
            const uint32_t d = pdst0 + (uint32_t)((s2 & 1) * B_BYTES);
#pragma unroll
            for (int i = 0; i < 8; i++) cp16(d + i * 16, s + i * 8);
            CP_COMMIT();
            CP_WAIT(1);
        } else {
            CP_WAIT(0);
        }
        __syncthreads();

        const uint32_t ab = aAddr + (uint32_t)(acol(c) * 2);
        const uint32_t bb = bAddr + (uint32_t)((step & 1) * B_BYTES);
#pragma unroll
        for (int ks = 0; ks < 8; ks++) {
            uint32_t a0[4], a1[4];
            ldsm4(a0, ab + ks * 32);
            ldsm4(a1, ab + ks * 32 + 16 * ASTRIDE * 2);
#pragma unroll
            for (int jj = 0; jj < 4; jj++) {
                uint32_t b[4];
                ldsm4(b, bb + ks * 32 + jj * 16 * BSTRIDE * 2);
                mma16816(acc[0][2 * jj],     a0, b[0], b[1]);
                mma16816(acc[0][2 * jj + 1], a0, b[2], b[3]);
                mma16816(acc[1][2 * jj],     a1, b[0], b[1]);
                mma16816(acc[1][2 * jj + 1], a1, b[2], b[3]);
            }
        }

        if (c == 5) {
            // Epilogue for n-tile nt: dist = cb_sq - 2*acc ; running argmin
            const int nbase = nt * 128 + wn * 64 + 2 * tig;
#pragma unroll
            for (int j = 0; j < 8; j++) {
                const int n0 = nbase + j * 8;
                const float cq0 = scs[n0];
                const float cq1 = scs[n0 + 1];
#pragma unroll
                for (int i = 0; i < 2; i++) {
                    const int s0 = i * 2, s1 = i * 2 + 1;
                    float d;
                    d = cq0 - 2.f * acc[i][j][0];
                    if (d < bestv[s0]) { bestv[s0] = d; besti[s0] = n0; }
                    d = cq1 - 2.f * acc[i][j][1];
                    if (d < bestv[s0]) { bestv[s0] = d; besti[s0] = n0 + 1; }
                    d = cq0 - 2.f * acc[i][j][2];
                    if (d < bestv[s1]) { bestv[s1] = d; besti[s1] = n0; }
                    d = cq1 - 2.f * acc[i][j][3];
                    if (d < bestv[s1]) { bestv[s1] = d; besti[s1] = n0 + 1; }
                }
            }
#pragma unroll
            for (int i = 0; i < 2; i++)
#pragma unroll
                for (int j = 0; j < 8; j++)
#pragma unroll
                    for (int x = 0; x < 4; x++) acc[i][j][x] = 0.f;
        }
        __syncthreads();
    }

    // Reduce over the 4 tig-lanes sharing each row (tie -> lower index)
#pragma unroll
    for (int o = 1; o < 4; o <<= 1) {
#pragma unroll
        for (int s = 0; s < 4; s++) {
            float ov = __shfl_xor_sync(0xffffffffu, bestv[s], o);
            int   oi = __shfl_xor_sync(0xffffffffu, besti[s], o);
            if (ov < bestv[s] || (ov == bestv[s] && oi < besti[s])) {
                bestv[s] = ov; besti[s] = oi;
            }
        }
    }

    // Cross warp-column reduce via smem (reuse B region)
    __syncthreads();
    float* rv = reinterpret_cast<float*>(smem + SM_B);          // [128][2]
    int*   ri = reinterpret_cast<int*>(smem + SM_B + 1024);     // [128][2]
    if (tig == 0) {
#pragma unroll
        for (int s = 0; s < 4; s++) {
            int row = wm * 32 + (s >> 1) * 16 + (s & 1) * 8 + gid;
            rv[row * 2 + wn] = bestv[s];
            ri[row * 2 + wn] = besti[s];
        }
    }
    __syncthreads();
    if (tid < 128) {
        float v0 = rv[tid * 2], v1 = rv[tid * 2 + 1];
        int i0 = ri[tid * 2], i1 = ri[tid * 2 + 1];
        int best = (v1 < v0 || (v1 == v0 && i1 < i0)) ? i1 : i0;
        g_idx[rowBase + tid] = best;
    }
}

// ---------------------------------------------------------------------------
// Kernel 2: gather + quantized_st + per-block masked losses (deterministic)
// ---------------------------------------------------------------------------
__global__ void gather_loss_kernel(const float* __restrict__ feat,
                                   const float* __restrict__ mask,
                                   const float* __restrict__ cb,
                                   float* __restrict__ outq) {
    __shared__ float sl[8];
    __shared__ float sd[8];
    const int warp = threadIdx.x >> 5;
    const int lane = threadIdx.x & 31;
    const int r = blockIdx.x * 8 + warp;

    const int idx = g_idx[r];
    const float* f = feat + (size_t)r * D_DIM;
    const float* w = cb + (size_t)idx * D_DIM;
    float* o = outq + (size_t)r * D_DIM;

    float s = 0.f;
#pragma unroll
    for (int u = 0; u < 2; u++) {
        int c = lane * 4 + u * 128;
        float4 fv = *reinterpret_cast<const float4*>(f + c);
        float4 wv = *reinterpret_cast<const float4*>(w + c);
        float4 ov;
        ov.x = fv.x + (wv.x - fv.x);
        ov.y = fv.y + (wv.y - fv.y);
        ov.z = fv.z + (wv.z - fv.z);
        ov.w = fv.w + (wv.w - fv.w);
        *reinterpret_cast<float4*>(o + c) = ov;
        float dx = fv.x - wv.x, dy = fv.y - wv.y;
        float dz = fv.z - wv.z, dw = fv.w - wv.w;
        s += dx * dx + dy * dy + dz * dz + dw * dw;
    }
#pragma unroll
    for (int of = 16; of > 0; of >>= 1) s += __shfl_down_sync(0xffffffffu, s, of);
    if (lane == 0) {
        float m = mask[r];
        sl[warp] = s * m;
        sd[warp] = m;
    }
    __syncthreads();
    if (threadIdx.x == 0) {
        float L = 0.f, Dn = 0.f;
#pragma unroll
        for (int i = 0; i < 8; i++) { L += sl[i]; Dn += sd[i]; }
        g_ploss[blockIdx.x] = L;
        g_pden[blockIdx.x] = Dn;
    }
}

// ---------------------------------------------------------------------------
// Kernel 3: per-batch reduce, write both losses
// ---------------------------------------------------------------------------
__global__ void finalize_kernel(float* __restrict__ out) {
    __shared__ float sl[256];
    __shared__ float sd[256];
    const int b = blockIdx.x, t = threadIdx.x;
    const int per = (M_ROWS / 8) / B_BATCH;   // 256
    sl[t] = g_ploss[b * per + t];
    sd[t] = g_pden[b * per + t];
    __syncthreads();
    for (int s = 128; s > 0; s >>= 1) {
        if (t < s) { sl[t] += sl[t + s]; sd[t] += sd[t + s]; }
        __syncthreads();
    }
    if (t == 0) {
        float loss = sl[0] / sd[0];
        size_t q = (size_t)M_ROWS * D_DIM;
        out[q + b] = loss;                 // quant_loss
        out[q + B_BATCH + b] = loss;       // commit_loss (numerically identical)
    }
}

// ---------------------------------------------------------------------------
extern "C" void kernel_launch(void* const* d_in, const int* in_sizes, int n_in,
                              void* d_out, int out_size) {
    const float* feat = (const float*)d_in[0];   // [16, 2048, 256] f32
    const float* mask = (const float*)d_in[1];   // [16, 2048] f32
    const float* cb   = (const float*)d_in[2];   // [1024, 256] f32
    float* out = (float*)d_out;

    cudaFuncSetAttribute(vq_mma_kernel,
                         cudaFuncAttributeMaxDynamicSharedMemorySize, SMEM_TOTAL);

    prep_kernel<<<K_CODES / 8, 256>>>(cb);
    vq_mma_kernel<<<M_ROWS / 128, 256, SMEM_TOTAL>>>(feat);
    gather_loss_kernel<<<M_ROWS / 8, 256>>>(feat, mask, cb, out);
    finalize_kernel<<<B_BATCH, 256>>>(out);
}

// round 16
// speedup vs baseline: 2.1373x; 1.0005x over previous
#include <cuda_runtime.h>
#include <cuda_fp16.h>
#include <cstdint>

// Problem dims (fixed)
#define B_BATCH 16
#define L_SEQ   2048
#define D_DIM   256
#define K_CODES 1024
#define M_ROWS  (B_BATCH * L_SEQ)   // 32768

// Scratch (device globals — no allocations allowed)
__device__ int    g_idx[M_ROWS];
__device__ float  g_cbsq[K_CODES];
__device__ __half g_b2[K_CODES * 2 * D_DIM];   // [1024][512] = [hi(256) | lo(256)]
__device__ float  g_ploss[M_ROWS / 8];
__device__ float  g_pden[M_ROWS / 8];

// ---------------------------------------------------------------------------
// GEMM kernel geometry
// ---------------------------------------------------------------------------
#define ASTRIDE 520                        // halfs/row; 260 words ≡ 4 mod 32 (conflict-free ldsm)
#define BSTRIDE 136                        // halfs/row; 68 words ≡ 4 mod 32
#define A_BYTES (128 * ASTRIDE * 2)        // 133120
#define B_BYTES (128 * BSTRIDE * 2)        // 34816
#define SM_A    0
#define SM_B    A_BYTES
#define SM_CS   (SM_B + 2 * B_BYTES)       // 202752
#define SMEM_TOTAL (SM_CS + 4096)          // 206848

#define NSTEPS 48                          // 8 n-tiles x 6 chunks (3 segments)

// ---------------------------------------------------------------------------
// PTX helpers (baseline sm_80+ instructions only — NO tcgen05)
// ---------------------------------------------------------------------------
__device__ __forceinline__ uint32_t smem_u32(const void* p) {
    uint32_t a;
    asm("{ .reg .u64 t; cvta.to.shared.u64 t, %1; cvt.u32.u64 %0, t; }"
        : "=r"(a) : "l"(p));
    return a;
}

__device__ __forceinline__ void cp16(uint32_t dst, const void* src) {
    asm volatile("cp.async.cg.shared.global [%0], [%1], 16;"
                 :: "r"(dst), "l"(src) : "memory");
}
#define CP_COMMIT() asm volatile("cp.async.commit_group;" ::: "memory")
#define CP_WAIT(n)  asm volatile("cp.async.wait_group %0;" :: "n"(n) : "memory")

__device__ __forceinline__ void ldsm4(uint32_t* r, uint32_t addr) {
    asm volatile("ldmatrix.sync.aligned.m8n8.x4.shared.b16 {%0,%1,%2,%3}, [%4];"
                 : "=r"(r[0]), "=r"(r[1]), "=r"(r[2]), "=r"(r[3]) : "r"(addr));
}

__device__ __forceinline__ void mma16816(float* c, const uint32_t* a,
                                         uint32_t b0, uint32_t b1) {
    asm volatile(
        "mma.sync.aligned.m16n8k16.row.col.f32.f16.f16.f32 "
        "{%0,%1,%2,%3}, {%4,%5,%6,%7}, {%8,%9}, {%0,%1,%2,%3};"
        : "+f"(c[0]), "+f"(c[1]), "+f"(c[2]), "+f"(c[3])
        : "r"(a[0]), "r"(a[1]), "r"(a[2]), "r"(a[3]), "r"(b0), "r"(b1));
}

__device__ __forceinline__ void split_h(float x, __half& hi, __half& lo) {
    hi = __float2half_rn(x);
    lo = __float2half_rn(x - __half2float(hi));
}

union H8 {
    __half h[8];
    uint4 u;
};

// ---------------------------------------------------------------------------
// Kernel 0: merged codebook prep — per-row norm (exact fp32) + fp16 hi|lo
// split into g_b2[1024][hi256|lo256]. One warp per codebook row.
// ---------------------------------------------------------------------------
__global__ void prep_kernel(const float* __restrict__ cb) {
    const int w = (blockIdx.x * blockDim.x + threadIdx.x) >> 5;   // 0..1023
    const int lane = threadIdx.x & 31;
    const float* row = cb + (size_t)w * D_DIM;
    float4 v0 = *reinterpret_cast<const float4*>(row + lane * 8);
    float4 v1 = *reinterpret_cast<const float4*>(row + lane * 8 + 4);

    float s = v0.x * v0.x + v0.y * v0.y + v0.z * v0.z + v0.w * v0.w +
              v1.x * v1.x + v1.y * v1.y + v1.z * v1.z + v1.w * v1.w;
#pragma unroll
    for (int o = 16; o > 0; o >>= 1) s += __shfl_down_sync(0xffffffffu, s, o);
    if (lane == 0) g_cbsq[w] = s;

    H8 hh, ll;
    split_h(v0.x, hh.h[0], ll.h[0]); split_h(v0.y, hh.h[1], ll.h[1]);
    split_h(v0.z, hh.h[2], ll.h[2]); split_h(v0.w, hh.h[3], ll.h[3]);
    split_h(v1.x, hh.h[4], ll.h[4]); split_h(v1.y, hh.h[5], ll.h[5]);
    split_h(v1.z, hh.h[6], ll.h[6]); split_h(v1.w, hh.h[7], ll.h[7]);
    __half* dh = g_b2 + (size_t)w * 512 + lane * 8;
    *reinterpret_cast<uint4*>(dh) = hh.u;
    *reinterpret_cast<uint4*>(dh + 256) = ll.u;
}

// ---------------------------------------------------------------------------
// Kernel 1: fp16x3-split HMMA GEMM + fused argmin.
// CTA: 128 rows x 1024 codes. 8 warps, warp tile 32x64. Effective K = 768
// (segments ah*bh, ah*bl, al*bh; lo*lo dropped — bounded by ~6e-5 vs O(1)
// argmin gaps). Flattened 48-step chunk pipeline, cp.async double-buffered
// continuously across n-tile boundaries.
// ---------------------------------------------------------------------------
__global__ void __launch_bounds__(256, 1)
vq_mma_kernel(const float* __restrict__ feat) {
    extern __shared__ char smem[];
    __half* As = reinterpret_cast<__half*>(smem + SM_A);
    float* scs = reinterpret_cast<float*>(smem + SM_CS);
    const uint32_t sb = smem_u32(smem);

    const int tid = threadIdx.x;
    const int wid = tid >> 5;
    const int lane = tid & 31;
    const int gid = lane >> 2;         // row group within fragment
    const int tig = lane & 3;          // col-pair within fragment
    const int wm = wid & 3;            // warp m-row (0..3) -> rows wm*32
    const int wn = wid >> 2;           // warp n-col (0..1) -> cols wn*64
    const int rowBase = blockIdx.x * 128;

    // cb_sq -> smem
#pragma unroll
    for (int i = 0; i < K_CODES / 256; i++)
        scs[tid + i * 256] = g_cbsq[tid + i * 256];

    // A fill + fp16 split: 128 rows x 256 fp32 -> [row][ah(0:256) | al(256:512)]
#pragma unroll
    for (int it = 0; it < 32; it++) {
        int u = tid + it * 256;          // 8192 quads
        int row = u >> 6;
        int q = u & 63;
        float4 v = *reinterpret_cast<const float4*>(
            feat + (size_t)(rowBase + row) * D_DIM + q * 4);
        __half h0, h1, h2, h3, l0, l1, l2, l3;
        split_h(v.x, h0, l0); split_h(v.y, h1, l1);
        split_h(v.z, h2, l2); split_h(v.w, h3, l3);
        __half2* ph = reinterpret_cast<__half2*>(As + row * ASTRIDE + q * 4);
        __half2* pl = reinterpret_cast<__half2*>(As + row * ASTRIDE + 256 + q * 4);
        ph[0] = __halves2half2(h0, h1);
        ph[1] = __halves2half2(h2, h3);
        pl[0] = __halves2half2(l0, l1);
        pl[1] = __halves2half2(l2, l3);
    }
    __syncthreads();

    // ldmatrix base addresses (bytes)
    const uint32_t aAddr = sb + SM_A +
        ((uint32_t)((wm * 32 + (lane & 15)) * ASTRIDE + (lane >> 4) * 8) * 2u);
    const int n_off = (lane & 7) + ((lane >> 4) & 1) * 8;
    const int k_off = ((lane >> 3) & 1) * 8;
    const uint32_t bAddr = sb + SM_B +
        ((uint32_t)((wn * 64 + n_off) * BSTRIDE + k_off) * 2u);

    float bestv[4] = {3.4e38f, 3.4e38f, 3.4e38f, 3.4e38f};
    int   besti[4] = {0, 0, 0, 0};

    // Chunk c (0..5) within an n-tile: c<2 -> ah*bh, c in 2..3 -> ah*bl,
    // c in 4..5 -> al*bh. Columns are halfs in the 512-wide split space.
    auto acol = [](int c) { return ((c >> 2) ? 256 : 0) + (c & 1) * 128; };
    auto bcol = [](int c) { return (((c >> 1) == 1) ? 256 : 0) + (c & 1) * 128; };

    const int pr = tid >> 1;             // prefetch row 0..127
    const int pc = (tid & 1) * 64;       // prefetch col half (halfs)
    const uint32_t pdst0 = sb + SM_B + (uint32_t)((pr * BSTRIDE + pc) * 2);

    float acc[2][8][4];
#pragma unroll
    for (int i = 0; i < 2; i++)
#pragma unroll
        for (int j = 0; j < 8; j++)
#pragma unroll
            for (int x = 0; x < 4; x++) acc[i][j][x] = 0.f;

    // prefetch step 0 -> buf 0
    {
        const __half* s = g_b2 + (size_t)pr * 512 + bcol(0) + pc;
#pragma unroll
        for (int i = 0; i < 8; i++) cp16(pdst0 + i * 16, s + i * 8);
        CP_COMMIT();
    }

#pragma unroll 1
    for (int step = 0; step < NSTEPS; step++) {
        const int nt = step / 6;
        const int c  = step - nt * 6;

        if (step < NSTEPS - 1) {
            const int s2 = step + 1;
            const int nt2 = s2 / 6;
            const int c2 = s2 - nt2 * 6;
            const __half* s = g_b2 + (size_t)(nt2 * 128 + pr) * 512 + bcol(c2) + pc;
            const uint32_t d = pdst0 + (uint32_t)((s2 & 1) * B_BYTES);
#pragma unroll
            for (int i = 0; i < 8; i++) cp16(d + i * 16, s + i * 8);
            CP_COMMIT();
            CP_WAIT(1);
        } else {
            CP_WAIT(0);
        }
        __syncthreads();

        const uint32_t ab = aAddr + (uint32_t)(acol(c) * 2);
        const uint32_t bb = bAddr + (uint32_t)((step & 1) * B_BYTES);
#pragma unroll
        for (int ks = 0; ks < 8; ks++) {
            uint32_t a0[4], a1[4];
            ldsm4(a0, ab + ks * 32);
            ldsm4(a1, ab + ks * 32 + 16 * ASTRIDE * 2);
#pragma unroll
            for (int jj = 0; jj < 4; jj++) {
                uint32_t b[4];
                ldsm4(b, bb + ks * 32 + jj * 16 * BSTRIDE * 2);
                mma16816(acc[0][2 * jj],     a0, b[0], b[1]);
                mma16816(acc[0][2 * jj + 1], a0, b[2], b[3]);
                mma16816(acc[1][2 * jj],     a1, b[0], b[1]);
                mma16816(acc[1][2 * jj + 1], a1, b[2], b[3]);
            }
        }

        if (c == 5) {
            // Epilogue for n-tile nt: dist = cb_sq - 2*acc ; running argmin
            const int nbase = nt * 128 + wn * 64 + 2 * tig;
#pragma unroll
            for (int j = 0; j < 8; j++) {
                const int n0 = nbase + j * 8;
                const float cq0 = scs[n0];
                const float cq1 = scs[n0 + 1];
#pragma unroll
                for (int i = 0; i < 2; i++) {
                    const int s0 = i * 2, s1 = i * 2 + 1;
                    float d;
                    d = cq0 - 2.f * acc[i][j][0];
                    if (d < bestv[s0]) { bestv[s0] = d; besti[s0] = n0; }
                    d = cq1 - 2.f * acc[i][j][1];
                    if (d < bestv[s0]) { bestv[s0] = d; besti[s0] = n0 + 1; }
                    d = cq0 - 2.f * acc[i][j][2];
                    if (d < bestv[s1]) { bestv[s1] = d; besti[s1] = n0; }
                    d = cq1 - 2.f * acc[i][j][3];
                    if (d < bestv[s1]) { bestv[s1] = d; besti[s1] = n0 + 1; }
                }
            }
#pragma unroll
            for (int i = 0; i < 2; i++)
#pragma unroll
                for (int j = 0; j < 8; j++)
#pragma unroll
                    for (int x = 0; x < 4; x++) acc[i][j][x] = 0.f;
        }
        __syncthreads();
    }

    // Reduce over the 4 tig-lanes sharing each row (tie -> lower index)
#pragma unroll
    for (int o = 1; o < 4; o <<= 1) {
#pragma unroll
        for (int s = 0; s < 4; s++) {
            float ov = __shfl_xor_sync(0xffffffffu, bestv[s], o);
            int   oi = __shfl_xor_sync(0xffffffffu, besti[s], o);
            if (ov < bestv[s] || (ov == bestv[s] && oi < besti[s])) {
                bestv[s] = ov; besti[s] = oi;
            }
        }
    }

    // Cross warp-column reduce via smem (reuse B region)
    __syncthreads();
    float* rv = reinterpret_cast<float*>(smem + SM_B);          // [128][2]
    int*   ri = reinterpret_cast<int*>(smem + SM_B + 1024);     // [128][2]
    if (tig == 0) {
#pragma unroll
        for (int s = 0; s < 4; s++) {
            int row = wm * 32 + (s >> 1) * 16 + (s & 1) * 8 + gid;
            rv[row * 2 + wn] = bestv[s];
            ri[row * 2 + wn] = besti[s];
        }
    }
    __syncthreads();
    if (tid < 128) {
        float v0 = rv[tid * 2], v1 = rv[tid * 2 + 1];
        int i0 = ri[tid * 2], i1 = ri[tid * 2 + 1];
        int best = (v1 < v0 || (v1 == v0 && i1 < i0)) ? i1 : i0;
        g_idx[rowBase + tid] = best;
    }
}

// ---------------------------------------------------------------------------
// Kernel 2: gather + quantized_st + per-block masked losses (deterministic)
// ---------------------------------------------------------------------------
__global__ void gather_loss_kernel(const float* __restrict__ feat,
                                   const float* __restrict__ mask,
                                   const float* __restrict__ cb,
                                   float* __restrict__ outq) {
    __shared__ float sl[8];
    __shared__ float sd[8];
    const int warp = threadIdx.x >> 5;
    const int lane = threadIdx.x & 31;
    const int r = blockIdx.x * 8 + warp;

    const int idx = g_idx[r];
    const float* f = feat + (size_t)r * D_DIM;
    const float* w = cb + (size_t)idx * D_DIM;
    float* o = outq + (size_t)r * D_DIM;

    float s = 0.f;
#pragma unroll
    for (int u = 0; u < 2; u++) {
        int c = lane * 4 + u * 128;
        float4 fv = *reinterpret_cast<const float4*>(f + c);
        float4 wv = *reinterpret_cast<const float4*>(w + c);
        float4 ov;
        ov.x = fv.x + (wv.x - fv.x);
        ov.y = fv.y + (wv.y - fv.y);
        ov.z = fv.z + (wv.z - fv.z);
        ov.w = fv.w + (wv.w - fv.w);
        *reinterpret_cast<float4*>(o + c) = ov;
        float dx = fv.x - wv.x, dy = fv.y - wv.y;
        float dz = fv.z - wv.z, dw = fv.w - wv.w;
        s += dx * dx + dy * dy + dz * dz + dw * dw;
    }
#pragma unroll
    for (int of = 16; of > 0; of >>= 1) s += __shfl_down_sync(0xffffffffu, s, of);
    if (lane == 0) {
        float m = mask[r];
        sl[warp] = s * m;
        sd[warp] = m;
    }
    __syncthreads();
    if (threadIdx.x == 0) {
        float L = 0.f, Dn = 0.f;
#pragma unroll
        for (int i = 0; i < 8; i++) { L += sl[i]; Dn += sd[i]; }
        g_ploss[blockIdx.x] = L;
        g_pden[blockIdx.x] = Dn;
    }
}

// ---------------------------------------------------------------------------
// Kernel 3: per-batch reduce, write both losses
// ---------------------------------------------------------------------------
__global__ void finalize_kernel(float* __restrict__ out) {
    __shared__ float sl[256];
    __shared__ float sd[256];
    const int b = blockIdx.x, t = threadIdx.x;
    const int per = (M_ROWS / 8) / B_BATCH;   // 256
    sl[t] = g_ploss[b * per + t];
    sd[t] = g_pden[b * per + t];
    __syncthreads();
    for (int s = 128; s > 0; s >>= 1) {
        if (t < s) { sl[t] += sl[t + s]; sd[t] += sd[t + s]; }
        __syncthreads();
    }
    if (t == 0) {
        float loss = sl[0] / sd[0];
        size_t q = (size_t)M_ROWS * D_DIM;
        out[q + b] = loss;                 // quant_loss
        out[q + B_BATCH + b] = loss;       // commit_loss (numerically identical)
    }
}

// ---------------------------------------------------------------------------
extern "C" void kernel_launch(void* const* d_in, const int* in_sizes, int n_in,
                              void* d_out, int out_size) {
    const float* feat = (const float*)d_in[0];   // [16, 2048, 256] f32
    const float* mask = (const float*)d_in[1];   // [16, 2048] f32
    const float* cb   = (const float*)d_in[2];   // [1024, 256] f32
    float* out = (float*)d_out;

    cudaFuncSetAttribute(vq_mma_kernel,
                         cudaFuncAttributeMaxDynamicSharedMemorySize, SMEM_TOTAL);

    prep_kernel<<<K_CODES / 8, 256>>>(cb);
    vq_mma_kernel<<<M_ROWS / 128, 256, SMEM_TOTAL>>>(feat);
    gather_loss_kernel<<<M_ROWS / 8, 256>>>(feat, mask, cb, out);
    finalize_kernel<<<B_BATCH, 256>>>(out);
}

// round 17
// speedup vs baseline: 2.2139x; 1.0358x over previous
#include <cuda_runtime.h>
#include <cuda_fp16.h>
#include <cstdint>

// Problem dims (fixed)
#define B_BATCH 16
#define L_SEQ   2048
#define D_DIM   256
#define K_CODES 1024
#define M_ROWS  (B_BATCH * L_SEQ)   // 32768

// Scratch (device globals — no allocations allowed)
__device__ int    g_idx_dummy;   // (unused; kept slot)
__device__ float  g_cbsq[K_CODES];
__device__ __half g_b2[K_CODES * 2 * D_DIM];     // [1024][hi256|lo256]
__device__ __half g_a2[M_ROWS * 2 * D_DIM];      // [32768][hi256|lo256] (32MB)
__device__ unsigned long long g_part[M_ROWS * 4];// per-row per-quarter (key|idx)
__device__ float  g_ploss[M_ROWS / 8];
__device__ float  g_pden[M_ROWS / 8];

// ---------------------------------------------------------------------------
// GEMM kernel geometry
// ---------------------------------------------------------------------------
#define ASTRIDE 520                        // halfs/row; 260 words ≡ 4 mod 32
#define BSTRIDE 136                        // halfs/row; 68 words ≡ 4 mod 32
#define A_BYTES (128 * ASTRIDE * 2)        // 133120
#define B_BYTES (128 * BSTRIDE * 2)        // 34816
#define SM_A    0
#define SM_B    A_BYTES
#define SM_CS   (SM_B + 2 * B_BYTES)       // 202752
#define SMEM_TOTAL (SM_CS + 4096)          // 206848

// ---------------------------------------------------------------------------
// PTX helpers (baseline sm_80+ instructions only — NO tcgen05)
// ---------------------------------------------------------------------------
__device__ __forceinline__ uint32_t smem_u32(const void* p) {
    uint32_t a;
    asm("{ .reg .u64 t; cvta.to.shared.u64 t, %1; cvt.u32.u64 %0, t; }"
        : "=r"(a) : "l"(p));
    return a;
}

__device__ __forceinline__ void cp16(uint32_t dst, const void* src) {
    asm volatile("cp.async.cg.shared.global [%0], [%1], 16;"
                 :: "r"(dst), "l"(src) : "memory");
}
#define CP_COMMIT() asm volatile("cp.async.commit_group;" ::: "memory")
#define CP_WAIT(n)  asm volatile("cp.async.wait_group %0;" :: "n"(n) : "memory")

__device__ __forceinline__ void ldsm4(uint32_t* r, uint32_t addr) {
    asm volatile("ldmatrix.sync.aligned.m8n8.x4.shared.b16 {%0,%1,%2,%3}, [%4];"
                 : "=r"(r[0]), "=r"(r[1]), "=r"(r[2]), "=r"(r[3]) : "r"(addr));
}

__device__ __forceinline__ void mma16816(float* c, const uint32_t* a,
                                         uint32_t b0, uint32_t b1) {
    asm volatile(
        "mma.sync.aligned.m16n8k16.row.col.f32.f16.f16.f32 "
        "{%0,%1,%2,%3}, {%4,%5,%6,%7}, {%8,%9}, {%0,%1,%2,%3};"
        : "+f"(c[0]), "+f"(c[1]), "+f"(c[2]), "+f"(c[3])
        : "r"(a[0]), "r"(a[1]), "r"(a[2]), "r"(a[3]), "r"(b0), "r"(b1));
}

__device__ __forceinline__ void split_h(float x, __half& hi, __half& lo) {
    hi = __float2half_rn(x);
    lo = __float2half_rn(x - __half2float(hi));
}

union H8 {
    __half h[8];
    uint4 u;
};

// Order-preserving float->u32 key; pack with idx so u64-min == (min dist,
// then min idx). Negative dists handled (dist = cbsq - 2s can be < 0).
__device__ __forceinline__ unsigned long long packdi(float d, int i) {
    uint32_t u = __float_as_uint(d);
    u = (u & 0x80000000u) ? ~u : (u | 0x80000000u);
    return ((unsigned long long)u << 32) | (uint32_t)i;
}

// ---------------------------------------------------------------------------
// Kernel 0a: codebook prep — per-row norm (exact fp32) + fp16 hi|lo split.
// One warp per codebook row.
// ---------------------------------------------------------------------------
__global__ void prep_kernel(const float* __restrict__ cb) {
    const int w = (blockIdx.x * blockDim.x + threadIdx.x) >> 5;   // 0..1023
    const int lane = threadIdx.x & 31;
    const float* row = cb + (size_t)w * D_DIM;
    float4 v0 = *reinterpret_cast<const float4*>(row + lane * 8);
    float4 v1 = *reinterpret_cast<const float4*>(row + lane * 8 + 4);

    float s = v0.x * v0.x + v0.y * v0.y + v0.z * v0.z + v0.w * v0.w +
              v1.x * v1.x + v1.y * v1.y + v1.z * v1.z + v1.w * v1.w;
#pragma unroll
    for (int o = 16; o > 0; o >>= 1) s += __shfl_down_sync(0xffffffffu, s, o);
    if (lane == 0) g_cbsq[w] = s;

    H8 hh, ll;
    split_h(v0.x, hh.h[0], ll.h[0]); split_h(v0.y, hh.h[1], ll.h[1]);
    split_h(v0.z, hh.h[2], ll.h[2]); split_h(v0.w, hh.h[3], ll.h[3]);
    split_h(v1.x, hh.h[4], ll.h[4]); split_h(v1.y, hh.h[5], ll.h[5]);
    split_h(v1.z, hh.h[6], ll.h[6]); split_h(v1.w, hh.h[7], ll.h[7]);
    __half* dh = g_b2 + (size_t)w * 512 + lane * 8;
    *reinterpret_cast<uint4*>(dh) = hh.u;
    *reinterpret_cast<uint4*>(dh + 256) = ll.u;
}

// ---------------------------------------------------------------------------
// Kernel 0b: feature prep — fp16 hi|lo split of all 32768 feature rows into
// g_a2 so per-tile A fills are pure cp.async (no per-tile split ALU).
// One warp per feature row.
// ---------------------------------------------------------------------------
__global__ void prep_a_kernel(const float* __restrict__ feat) {
    const int w = (blockIdx.x * blockDim.x + threadIdx.x) >> 5;   // 0..32767
    const int lane = threadIdx.x & 31;
    const float* row = feat + (size_t)w * D_DIM;
    float4 v0 = *reinterpret_cast<const float4*>(row + lane * 8);
    float4 v1 = *reinterpret_cast<const float4*>(row + lane * 8 + 4);

    H8 hh, ll;
    split_h(v0.x, hh.h[0], ll.h[0]); split_h(v0.y, hh.h[1], ll.h[1]);
    split_h(v0.z, hh.h[2], ll.h[2]); split_h(v0.w, hh.h[3], ll.h[3]);
    split_h(v1.x, hh.h[4], ll.h[4]); split_h(v1.y, hh.h[5], ll.h[5]);
    split_h(v1.z, hh.h[6], ll.h[6]); split_h(v1.w, hh.h[7], ll.h[7]);
    __half* dh = g_a2 + (size_t)w * 512 + lane * 8;
    *reinterpret_cast<uint4*>(dh) = hh.u;
    *reinterpret_cast<uint4*>(dh + 256) = ll.u;
}

// ---------------------------------------------------------------------------
// Kernel 1: fp16x3-split HMMA GEMM + fused partial argmin.
// QUARTER TILES: each CTA = 128 rows x 256 codes (grid 1024, rowblock-major)
// -> 7 waves instead of 2 -> ~98% wave utilization (was 86.5%).
// 12 steps/tile (2 code-halves x 3 segments x 2 k-halves), cp.async
// double-buffered; A filled by cp.async from pre-split g_a2, overlapped with
// the B pipeline. Emits per-row packed (key|idx) u64 partial per quarter.
// ---------------------------------------------------------------------------
__global__ void __launch_bounds__(256, 1)
vq_mma_kernel() {
    extern __shared__ char smem[];
    float* scs = reinterpret_cast<float*>(smem + SM_CS);
    const uint32_t sb = smem_u32(smem);

    const int tid = threadIdx.x;
    const int wid = tid >> 5;
    const int lane = tid & 31;
    const int gid = lane >> 2;         // row group within fragment
    const int tig = lane & 3;          // col-pair within fragment
    const int wm = wid & 3;            // warp m-row (0..3) -> rows wm*32
    const int wn = wid >> 2;           // warp n-col (0..1) -> cols wn*64
    const int rb = blockIdx.x >> 2;    // rowblock (rowblock-major for A reuse)
    const int q  = blockIdx.x & 3;     // code quarter
    const int rowBase = rb * 128;
    const int codeBase = q * 256;

    // A fill via cp.async from pre-split g_a2: 128 rows x 1024B
#pragma unroll
    for (int it = 0; it < 32; it++) {
        int u = tid + it * 256;          // 8192 x 16B
        int row = u >> 6;
        int c16 = u & 63;
        cp16(sb + SM_A + (uint32_t)(row * (ASTRIDE * 2) + c16 * 16),
             g_a2 + (size_t)(rowBase + row) * 512 + c16 * 8);
    }
    CP_COMMIT();                        // group gA

    // cb_sq -> smem (all 1024; indexed globally)
#pragma unroll
    for (int i = 0; i < K_CODES / 256; i++)
        scs[tid + i * 256] = g_cbsq[tid + i * 256];

    // Chunk c (0..5) within a 128-code group: c0,c1 = ah*bh; c2,c3 = ah*bl;
    // c4,c5 = al*bh. Columns are halfs in the 512-wide split space.
    auto acol = [](int c) { return ((c >> 2) ? 256 : 0) + (c & 1) * 128; };
    auto bcol = [](int c) { return (((c >> 1) == 1) ? 256 : 0) + (c & 1) * 128; };

    const int pr = tid >> 1;             // prefetch row 0..127
    const int pc = (tid & 1) * 64;       // prefetch col half (halfs)
    const uint32_t pdst0 = sb + SM_B + (uint32_t)((pr * BSTRIDE + pc) * 2);

    // prefetch step 0 -> buf 0
    {
        const __half* s = g_b2 + (size_t)(codeBase + pr) * 512 + bcol(0) + pc;
#pragma unroll
        for (int i = 0; i < 8; i++) cp16(pdst0 + i * 16, s + i * 8);
        CP_COMMIT();
    }

    // ldmatrix base addresses (bytes)
    const uint32_t aAddr = sb + SM_A +
        ((uint32_t)((wm * 32 + (lane & 15)) * ASTRIDE + (lane >> 4) * 8) * 2u);
    const int n_off = (lane & 7) + ((lane >> 4) & 1) * 8;
    const int k_off = ((lane >> 3) & 1) * 8;
    const uint32_t bAddr = sb + SM_B +
        ((uint32_t)((wn * 64 + n_off) * BSTRIDE + k_off) * 2u);

    float bestv[4] = {3.4e38f, 3.4e38f, 3.4e38f, 3.4e38f};
    int   besti[4] = {0, 0, 0, 0};

    float acc[2][8][4];
#pragma unroll
    for (int i = 0; i < 2; i++)
#pragma unroll
        for (int j = 0; j < 8; j++)
#pragma unroll
            for (int x = 0; x < 4; x++) acc[i][j][x] = 0.f;

#pragma unroll 1
    for (int step = 0; step < 12; step++) {
        const int nt = step / 6;         // code half within quarter (0/1)
        const int c  = step - nt * 6;

        if (step < 11) {
            const int s2 = step + 1;
            const int nt2 = s2 / 6;
            const int c2 = s2 - nt2 * 6;
            const __half* s = g_b2 +
                (size_t)(codeBase + nt2 * 128 + pr) * 512 + bcol(c2) + pc;
            const uint32_t d = pdst0 + (uint32_t)((s2 & 1) * B_BYTES);
#pragma unroll
            for (int i = 0; i < 8; i++) cp16(d + i * 16, s + i * 8);
            CP_COMMIT();
            CP_WAIT(1);                 // drains gA + all but newest B group
        } else {
            CP_WAIT(0);
        }
        __syncthreads();

        const uint32_t ab = aAddr + (uint32_t)(acol(c) * 2);
        const uint32_t bb = bAddr + (uint32_t)((step & 1) * B_BYTES);
#pragma unroll
        for (int ks = 0; ks < 8; ks++) {
            uint32_t a0[4], a1[4];
            ldsm4(a0, ab + ks * 32);
            ldsm4(a1, ab + ks * 32 + 16 * ASTRIDE * 2);
#pragma unroll
            for (int jj = 0; jj < 4; jj++) {
                uint32_t b[4];
                ldsm4(b, bb + ks * 32 + jj * 16 * BSTRIDE * 2);
                mma16816(acc[0][2 * jj],     a0, b[0], b[1]);
                mma16816(acc[0][2 * jj + 1], a0, b[2], b[3]);
                mma16816(acc[1][2 * jj],     a1, b[0], b[1]);
                mma16816(acc[1][2 * jj + 1], a1, b[2], b[3]);
            }
        }

        if (c == 5) {
            // Epilogue for code group: dist = cb_sq - 2*acc ; running argmin
            const int nbase = codeBase + nt * 128 + wn * 64 + 2 * tig;
#pragma unroll
            for (int j = 0; j < 8; j++) {
                const int n0 = nbase + j * 8;
                const float cq0 = scs[n0];
                const float cq1 = scs[n0 + 1];
#pragma unroll
                for (int i = 0; i < 2; i++) {
                    const int s0 = i * 2, s1 = i * 2 + 1;
                    float d;
                    d = cq0 - 2.f * acc[i][j][0];
                    if (d < bestv[s0]) { bestv[s0] = d; besti[s0] = n0; }
                    d = cq1 - 2.f * acc[i][j][1];
                    if (d < bestv[s0]) { bestv[s0] = d; besti[s0] = n0 + 1; }
                    d = cq0 - 2.f * acc[i][j][2];
                    if (d < bestv[s1]) { bestv[s1] = d; besti[s1] = n0; }
                    d = cq1 - 2.f * acc[i][j][3];
                    if (d < bestv[s1]) { bestv[s1] = d; besti[s1] = n0 + 1; }
                }
            }
#pragma unroll
            for (int i = 0; i < 2; i++)
#pragma unroll
                for (int j = 0; j < 8; j++)
#pragma unroll
                    for (int x = 0; x < 4; x++) acc[i][j][x] = 0.f;
        }
        __syncthreads();
    }

    // Reduce over the 4 tig-lanes sharing each row (tie -> lower index)
#pragma unroll
    for (int o = 1; o < 4; o <<= 1) {
#pragma unroll
        for (int s = 0; s < 4; s++) {
            float ov = __shfl_xor_sync(0xffffffffu, bestv[s], o);
            int   oi = __shfl_xor_sync(0xffffffffu, besti[s], o);
            if (ov < bestv[s] || (ov == bestv[s] && oi < besti[s])) {
                bestv[s] = ov; besti[s] = oi;
            }
        }
    }

    // Cross warp-column reduce via smem (reuse B region), emit u64 partial
    __syncthreads();
    unsigned long long* r64 =
        reinterpret_cast<unsigned long long*>(smem + SM_B);      // [128][2]
    if (tig == 0) {
#pragma unroll
        for (int s = 0; s < 4; s++) {
            int row = wm * 32 + (s >> 1) * 16 + (s & 1) * 8 + gid;
            r64[row * 2 + wn] = packdi(bestv[s], besti[s]);
        }
    }
    __syncthreads();
    if (tid < 128) {
        unsigned long long a = r64[tid * 2], b = r64[tid * 2 + 1];
        g_part[(size_t)(rowBase + tid) * 4 + q] = (b < a) ? b : a;
    }
}

// ---------------------------------------------------------------------------
// Kernel 2: merge quarter partials + gather + quantized_st + masked losses
// (deterministic: no atomics).
// ---------------------------------------------------------------------------
__global__ void gather_loss_kernel(const float* __restrict__ feat,
                                   const float* __restrict__ mask,
                                   const float* __restrict__ cb,
                                   float* __restrict__ outq) {
    __shared__ float sl[8];
    __shared__ float sd[8];
    const int warp = threadIdx.x >> 5;
    const int lane = threadIdx.x & 31;
    const int r = blockIdx.x * 8 + warp;

    // merge 4 quarter partials (u64 min == min dist, then min idx)
    int idx = 0;
    if (lane == 0) {
        const unsigned long long* p = g_part + (size_t)r * 4;
        unsigned long long m = p[0];
        if (p[1] < m) m = p[1];
        if (p[2] < m) m = p[2];
        if (p[3] < m) m = p[3];
        idx = (int)(uint32_t)m;
    }
    idx = __shfl_sync(0xffffffffu, idx, 0);

    const float* f = feat + (size_t)r * D_DIM;
    const float* w = cb + (size_t)idx * D_DIM;
    float* o = outq + (size_t)r * D_DIM;

    float s = 0.f;
#pragma unroll
    for (int u = 0; u < 2; u++) {
        int c = lane * 4 + u * 128;
        float4 fv = *reinterpret_cast<const float4*>(f + c);
        float4 wv = *reinterpret_cast<const float4*>(w + c);
        float4 ov;
        ov.x = fv.x + (wv.x - fv.x);
        ov.y = fv.y + (wv.y - fv.y);
        ov.z = fv.z + (wv.z - fv.z);
        ov.w = fv.w + (wv.w - fv.w);
        *reinterpret_cast<float4*>(o + c) = ov;
        float dx = fv.x - wv.x, dy = fv.y - wv.y;
        float dz = fv.z - wv.z, dw = fv.w - wv.w;
        s += dx * dx + dy * dy + dz * dz + dw * dw;
    }
#pragma unroll
    for (int of = 16; of > 0; of >>= 1) s += __shfl_down_sync(0xffffffffu, s, of);
    if (lane == 0) {
        float m = mask[r];
        sl[warp] = s * m;
        sd[warp] = m;
    }
    __syncthreads();
    if (threadIdx.x == 0) {
        float L = 0.f, Dn = 0.f;
#pragma unroll
        for (int i = 0; i < 8; i++) { L += sl[i]; Dn += sd[i]; }
        g_ploss[blockIdx.x] = L;
        g_pden[blockIdx.x] = Dn;
    }
}

// ---------------------------------------------------------------------------
// Kernel 3: per-batch reduce, write both losses
// ---------------------------------------------------------------------------
__global__ void finalize_kernel(float* __restrict__ out) {
    __shared__ float sl[256];
    __shared__ float sd[256];
    const int b = blockIdx.x, t = threadIdx.x;
    const int per = (M_ROWS / 8) / B_BATCH;   // 256
    sl[t] = g_ploss[b * per + t];
    sd[t] = g_pden[b * per + t];
    __syncthreads();
    for (int s = 128; s > 0; s >>= 1) {
        if (t < s) { sl[t] += sl[t + s]; sd[t] += sd[t + s]; }
        __syncthreads();
    }
    if (t == 0) {
        float loss = sl[0] / sd[0];
        size_t q = (size_t)M_ROWS * D_DIM;
        out[q + b] = loss;                 // quant_loss
        out[q + B_BATCH + b] = loss;       // commit_loss (numerically identical)
    }
}

// ---------------------------------------------------------------------------
extern "C" void kernel_launch(void* const* d_in, const int* in_sizes, int n_in,
                              void* d_out, int out_size) {
    const float* feat = (const float*)d_in[0];   // [16, 2048, 256] f32
    const float* mask = (const float*)d_in[1];   // [16, 2048] f32
    const float* cb   = (const float*)d_in[2];   // [1024, 256] f32
    float* out = (float*)d_out;

    cudaFuncSetAttribute(vq_mma_kernel,
                         cudaFuncAttributeMaxDynamicSharedMemorySize, SMEM_TOTAL);

    prep_kernel<<<K_CODES / 8, 256>>>(cb);
    prep_a_kernel<<<M_ROWS / 8, 256>>>(feat);
    vq_mma_kernel<<<(M_ROWS / 128) * 4, 256, SMEM_TOTAL>>>();
    gather_loss_kernel<<<M_ROWS / 8, 256>>>(feat, mask, cb, out);
    finalize_kernel<<<B_BATCH, 256>>>(out);
}